// round 13
// baseline (speedup 1.0000x reference)
#include <cuda_runtime.h>
#include <cuda_fp16.h>
#include <math_constants.h>
#include <cstdint>

#define TDIM   1024
#define DDIM   1024
#define NBATCH 8
#define NHEADS 16
#define MROWS  (NBATCH * TDIM)   // 8192

// Q pre-scale: 1/sqrt(64) * log2(e)  (exp2-domain softmax)
#define QSCALE 0.18033688011112042f

// ---------------- scratch (__device__ globals) ------------------------------
__device__ __align__(256) __half g_x [MROWS * DDIM];
__device__ __align__(256) __half g_q [MROWS * DDIM];
__device__ __align__(256) __half g_k [MROWS * DDIM];
__device__ __align__(256) __half g_v [MROWS * DDIM];
__device__ __align__(256) __half g_att[MROWS * DDIM];
__device__ __align__(256) __half g_wq[DDIM * DDIM];
__device__ __align__(256) __half g_wk[DDIM * DDIM];
__device__ __align__(256) __half g_wv[DDIM * DDIM];
__device__ __align__(256) __half g_wo[DDIM * DDIM];

// ---------------- PTX helpers ----------------------------------------------
__device__ __forceinline__ uint32_t smem_u32(const void* p) {
    uint32_t a;
    asm("{ .reg .u64 t; cvta.to.shared.u64 t, %1; cvt.u32.u64 %0, t; }" : "=r"(a) : "l"(p));
    return a;
}
__device__ __forceinline__ void cp16(uint32_t dst, const void* src) {
    asm volatile("cp.async.cg.shared.global [%0], [%1], 16;" :: "r"(dst), "l"(src));
}
#define CP_COMMIT()  asm volatile("cp.async.commit_group;" ::: "memory")
#define CP_WAIT(n)   asm volatile("cp.async.wait_group %0;" :: "n"(n) : "memory")

#define LDSM_X4(r0, r1, r2, r3, a)                                                 \
    asm volatile("ldmatrix.sync.aligned.m8n8.x4.shared.b16 {%0,%1,%2,%3}, [%4];"   \
                 : "=r"(r0), "=r"(r1), "=r"(r2), "=r"(r3) : "r"(a))
#define LDSM_X4_T(r0, r1, r2, r3, a)                                               \
    asm volatile("ldmatrix.sync.aligned.m8n8.x4.trans.shared.b16 {%0,%1,%2,%3}, [%4];" \
                 : "=r"(r0), "=r"(r1), "=r"(r2), "=r"(r3) : "r"(a))

__device__ __forceinline__ void mma16816(float* c, const uint32_t* a, const uint32_t* b)
{
    asm volatile(
        "mma.sync.aligned.m16n8k16.row.col.f32.f16.f16.f32 "
        "{%0,%1,%2,%3}, {%4,%5,%6,%7}, {%8,%9}, {%0,%1,%2,%3};"
        : "+f"(c[0]), "+f"(c[1]), "+f"(c[2]), "+f"(c[3])
        : "r"(a[0]), "r"(a[1]), "r"(a[2]), "r"(a[3]), "r"(b[0]), "r"(b[1]));
}

__device__ __forceinline__ uint32_t pack_h(float a, float b)
{
    __half2 H(__float2half_rn(a), __float2half_rn(b));
    return *(uint32_t*)&H;
}
__device__ __forceinline__ float ex2f(float x)
{
    float r;
    asm("ex2.approx.f32 %0, %1;" : "=f"(r) : "f"(x));
    return r;
}

// ---------------------------------------------------------------------------
// Shared GEMM smem layout constants (both variants)
// ---------------------------------------------------------------------------
#define STRIDE 80
#define OPB    10240               // 128 rows * 80B
#define STGB   (2 * OPB)           // A, B
#define NSTG   3
#define SMEM_DYN (NSTG * STGB)     // 61440

// ---------------------------------------------------------------------------
// qkv GEMM (round-8 best config): 512 thr, 16 warps 4x4, warp tile 32x32.
// C = A · B^T, fp32 accum; epilogue: scale + single fp16 out.
// ---------------------------------------------------------------------------
__device__ __forceinline__ void hmma_gemm_qkv(const __half* __restrict__ A,
                                              const __half* __restrict__ B,
                                              __half* __restrict__ C1,
                                              float scale)
{
    extern __shared__ char smraw[];
    const uint32_t s0 = smem_u32(smraw);

    const int tid  = threadIdx.x;
    const int warp = tid >> 5;
    const int lane = tid & 31;
    const int m0   = blockIdx.y * 128;
    const int n0   = blockIdx.x * 128;
    const int wm   = (warp >> 2) * 32;
    const int wn   = (warp & 3) * 32;

    const char* ga = (const char*)(A + (size_t)m0 * DDIM);
    const char* gb = (const char*)(B + (size_t)n0 * DDIM);
    const int lrow = tid >> 2, lc = tid & 3;
    const size_t goff = (size_t)lrow * 2048 + lc * 16;
    const uint32_t soff = (uint32_t)lrow * STRIDE + lc * 16;

#define LOAD_STAGE_Q(kc, st)                                                   \
    {                                                                          \
        const uint32_t sb = s0 + (st) * STGB + soff;                           \
        const size_t go = goff + (kc) * 64;                                    \
        cp16(sb,       ga + go);                                               \
        cp16(sb + OPB, gb + go);                                               \
    }

    float acc[2][4][4];
#pragma unroll
    for (int i = 0; i < 2; i++)
#pragma unroll
        for (int j = 0; j < 4; j++)
#pragma unroll
            for (int r = 0; r < 4; r++) acc[i][j][r] = 0.f;

    LOAD_STAGE_Q(0, 0); CP_COMMIT();
    LOAD_STAGE_Q(1, 1); CP_COMMIT();

    const int arow_b = (lane & 15);
    const int ahalf  = (lane >> 4);

    for (int i = 0; i < 32; i++) {
        if (i < 30) { CP_WAIT(1); } else if (i == 30) { CP_WAIT(0); }
        __syncthreads();
        if (i < 30) { LOAD_STAGE_Q(i + 2, (i + 2) % NSTG); CP_COMMIT(); }

        const uint32_t base = s0 + (i % NSTG) * STGB;
#pragma unroll
        for (int g = 0; g < 2; g++) {
            const uint32_t coff = (uint32_t)(2 * g + ahalf) * 16;
            uint32_t af[2][4], bf[4][2];
#pragma unroll
            for (int mi = 0; mi < 2; mi++) {
                const uint32_t ra = (uint32_t)(wm + mi * 16 + arow_b) * STRIDE + coff;
                LDSM_X4(af[mi][0], af[mi][1], af[mi][2], af[mi][3], base + ra);
            }
#pragma unroll
            for (int jp = 0; jp < 2; jp++) {
                const uint32_t rbo = (uint32_t)(wn + jp * 16 + arow_b) * STRIDE + coff;
                uint32_t t0, t1, t2, t3;
                LDSM_X4(t0, t1, t2, t3, base + OPB + rbo);
                bf[2 * jp][0] = t0; bf[2 * jp][1] = t2;
                bf[2 * jp + 1][0] = t1; bf[2 * jp + 1][1] = t3;
            }
#pragma unroll
            for (int mi = 0; mi < 2; mi++)
#pragma unroll
                for (int nj = 0; nj < 4; nj++)
                    mma16816(acc[mi][nj], af[mi], bf[nj]);
        }
    }

    const int crow = lane >> 2;
    const int ccol = (lane & 3) * 2;
#pragma unroll
    for (int mi = 0; mi < 2; mi++)
#pragma unroll
        for (int nj = 0; nj < 4; nj++) {
            const size_t r0 = (size_t)(m0 + wm + mi * 16 + crow) * DDIM + (n0 + wn + nj * 8 + ccol);
            *(uint32_t*)(C1 + r0) = pack_h(acc[mi][nj][0] * scale, acc[mi][nj][1] * scale);
            *(uint32_t*)(C1 + r0 + 8 * DDIM) = pack_h(acc[mi][nj][2] * scale, acc[mi][nj][3] * scale);
        }
#undef LOAD_STAGE_Q
}

__global__ void __launch_bounds__(512, 1) qkv_tc_kernel()
{
    if (blockIdx.z == 0)                       // Q pre-scaled into exp2 domain
        hmma_gemm_qkv(g_x, g_wq, g_q, QSCALE);
    else if (blockIdx.z == 1)
        hmma_gemm_qkv(g_x, g_wk, g_k, 1.0f);
    else
        hmma_gemm_qkv(g_x, g_wv, g_v, 1.0f);
}

// ---------------------------------------------------------------------------
// out GEMM: 256 thr, 8 warps 2x4, warp tile 64x32, 2 CTAs/SM -> its 512-CTA
// grid runs as 1.73 waves of 296 instead of 3.46 waves of 148 (smaller tail).
// fp32 epilogue to d_out.
// ---------------------------------------------------------------------------
__global__ void __launch_bounds__(256, 2) out_tc_kernel(float* __restrict__ out)
{
    extern __shared__ char smraw[];
    const uint32_t s0 = smem_u32(smraw);

    const int tid  = threadIdx.x;
    const int warp = tid >> 5;
    const int lane = tid & 31;
    const int m0   = blockIdx.y * 128;
    const int n0   = blockIdx.x * 128;
    const int wm   = (warp >> 2) * 64;
    const int wn   = (warp & 3) * 32;

    const char* ga = (const char*)(g_att + (size_t)m0 * DDIM);
    const char* gb = (const char*)(g_wo  + (size_t)n0 * DDIM);
    const int lrow = tid >> 2, lc = tid & 3;            // 64 rows x 4 segs
    const size_t g0 = (size_t)lrow * 2048 + lc * 16;
    const size_t g1 = (size_t)(64 + lrow) * 2048 + lc * 16;
    const uint32_t sm0 = (uint32_t)lrow * STRIDE + lc * 16;
    const uint32_t sm1 = (uint32_t)(64 + lrow) * STRIDE + lc * 16;

#define LOAD_STAGE_O(kc, st)                                                   \
    {                                                                          \
        const uint32_t sb = s0 + (st) * STGB;                                  \
        const size_t ko = (size_t)(kc) * 64;                                   \
        cp16(sb + sm0,       ga + g0 + ko);                                    \
        cp16(sb + sm1,       ga + g1 + ko);                                    \
        cp16(sb + OPB + sm0, gb + g0 + ko);                                    \
        cp16(sb + OPB + sm1, gb + g1 + ko);                                    \
    }

    float acc[4][4][4];
#pragma unroll
    for (int i = 0; i < 4; i++)
#pragma unroll
        for (int j = 0; j < 4; j++)
#pragma unroll
            for (int r = 0; r < 4; r++) acc[i][j][r] = 0.f;

    LOAD_STAGE_O(0, 0); CP_COMMIT();
    LOAD_STAGE_O(1, 1); CP_COMMIT();

    const int arow_b = (lane & 15);
    const int ahalf  = (lane >> 4);

    for (int i = 0; i < 32; i++) {
        if (i < 30) { CP_WAIT(1); } else if (i == 30) { CP_WAIT(0); }
        __syncthreads();
        if (i < 30) { LOAD_STAGE_O(i + 2, (i + 2) % NSTG); CP_COMMIT(); }

        const uint32_t base = s0 + (i % NSTG) * STGB;
#pragma unroll
        for (int g = 0; g < 2; g++) {
            const uint32_t coff = (uint32_t)(2 * g + ahalf) * 16;
            uint32_t af[4][4], bf[4][2];
#pragma unroll
            for (int mi = 0; mi < 4; mi++) {
                const uint32_t ra = (uint32_t)(wm + mi * 16 + arow_b) * STRIDE + coff;
                LDSM_X4(af[mi][0], af[mi][1], af[mi][2], af[mi][3], base + ra);
            }
#pragma unroll
            for (int jp = 0; jp < 2; jp++) {
                const uint32_t rbo = (uint32_t)(wn + jp * 16 + arow_b) * STRIDE + coff;
                uint32_t t0, t1, t2, t3;
                LDSM_X4(t0, t1, t2, t3, base + OPB + rbo);
                bf[2 * jp][0] = t0; bf[2 * jp][1] = t2;
                bf[2 * jp + 1][0] = t1; bf[2 * jp + 1][1] = t3;
            }
#pragma unroll
            for (int mi = 0; mi < 4; mi++)
#pragma unroll
                for (int nj = 0; nj < 4; nj++)
                    mma16816(acc[mi][nj], af[mi], bf[nj]);
        }
    }

    const int crow = lane >> 2;
    const int ccol = (lane & 3) * 2;
#pragma unroll
    for (int mi = 0; mi < 4; mi++)
#pragma unroll
        for (int nj = 0; nj < 4; nj++) {
            float* p = out + (size_t)(m0 + wm + mi * 16 + crow) * DDIM + (n0 + wn + nj * 8 + ccol);
            *(float2*)p = make_float2(acc[mi][nj][0], acc[mi][nj][1]);
            *(float2*)(p + 8 * DDIM) = make_float2(acc[mi][nj][2], acc[mi][nj][3]);
        }
#undef LOAD_STAGE_O
}

// ---------------------------------------------------------------------------
// fused conversions (single fp16): blocks 0..8191 -> x, 8192.. -> weights
// ---------------------------------------------------------------------------
__global__ void __launch_bounds__(256) cvt_kernel(const float4* __restrict__ x,
                                                  const float4* __restrict__ wk,
                                                  const float4* __restrict__ wq,
                                                  const float4* __restrict__ wv,
                                                  const float4* __restrict__ wo)
{
    const int blk = blockIdx.x;
    const float4* src;
    __half* dst;
    int i;
    if (blk < 8192) {
        src = x; dst = g_x;
        i = blk * 256 + threadIdx.x;
    } else {
        const int wsel = (blk - 8192) >> 10;          // 1024 blocks per weight
        i = ((blk - 8192) & 1023) * 256 + threadIdx.x;
        switch (wsel) {
            case 0:  src = wq; dst = g_wq; break;
            case 1:  src = wk; dst = g_wk; break;
            case 2:  src = wv; dst = g_wv; break;
            default: src = wo; dst = g_wo; break;
        }
    }
    float4 v = src[i];
    ((uint32_t*)dst)[2 * i]     = pack_h(v.x, v.y);
    ((uint32_t*)dst)[2 * i + 1] = pack_h(v.z, v.w);
}

// ---------------------------------------------------------------------------
// Tensor-core causal flash attention: fp32 accum, fp16 Q/K/V/P, exp2-domain
// softmax, ones-column MMA row-sum, single __syncthreads per KV tile.
// Mask refinement: tile nt-1 masks all warps; tile nt-2 only warps 0-3
// (rows qb..qb+63 vs cols qb..qb+63).
// ---------------------------------------------------------------------------
#define AT_ROWB  144
#define AT_OP    9216              // 64 * 144
#define AT_STG   (2 * AT_OP)       // k, v
#define AT_NST   3
#define AT_SMEM  (AT_NST * AT_STG) // 55296 (covers Q staging 18432)

__global__ void __launch_bounds__(256, 2) attn_tc_kernel()
{
    extern __shared__ char smraw[];
    const uint32_t s0 = smem_u32(smraw);
    const int tid  = threadIdx.x;
    const int warp = tid >> 5;
    const int lane = tid & 31;
    const int y    = 7 - (int)blockIdx.x;      // heavy blocks first
    const int bh   = blockIdx.y;
    const int b    = bh >> 4, h = bh & 15;
    const int qb   = y * 128;
    const int nt   = 2 * y + 2;                // KV tiles of 64
    const size_t rb = (size_t)b * TDIM;

    // ---- stage Q 128x64 -> smem, then ldmatrix to regs ---------------------
    {
        const __half* src = g_q + (rb + qb) * DDIM + h * 64;
#pragma unroll
        for (int j = 0; j < 4; j++) {
            int id = tid + (j << 8);            // 0..1023
            int row = id >> 3, c = id & 7;
            cp16(s0 + row * AT_ROWB + c * 16, src + (size_t)row * DDIM + c * 8);
        }
        CP_COMMIT(); CP_WAIT(0);
        __syncthreads();
    }

    const int l15 = lane & 15, lh = lane >> 4;
    uint32_t qf[4][4];
#pragma unroll
    for (int ks = 0; ks < 4; ks++) {
        uint32_t ad = s0 + (uint32_t)(warp * 16 + l15) * AT_ROWB
                      + (uint32_t)(ks * 16 + lh * 8) * 2;
        LDSM_X4(qf[ks][0], qf[ks][1], qf[ks][2], qf[ks][3], ad);
    }
    __syncthreads();   // Q smem region free before KV loads reuse it

    float O[8][4], O1[4], m[2];
    m[0] = m[1] = -1e30f;
#pragma unroll
    for (int nj = 0; nj < 8; nj++)
#pragma unroll
        for (int c = 0; c < 4; c++) O[nj][c] = 0.f;
#pragma unroll
    for (int c = 0; c < 4; c++) O1[c] = 0.f;

    const int crow = lane >> 2, ccol = (lane & 3) * 2;
    const uint32_t ones2 = 0x3C003C00u;        // (1.0h, 1.0h)
    const uint32_t bones[2] = {ones2, ones2};

#define KV_LOAD(t, st)                                                              \
    {                                                                               \
        const __half* kb_ = g_k + (rb + (t) * 64) * DDIM + h * 64;                  \
        const __half* vb_ = g_v + (rb + (t) * 64) * DDIM + h * 64;                  \
        const uint32_t ds = s0 + (st) * AT_STG;                                     \
        _Pragma("unroll")                                                           \
        for (int j = 0; j < 4; j++) {                                               \
            int id = tid + (j << 8);                                                \
            int tile = id >> 9;                                                     \
            int within = id & 511;                                                  \
            int row = within >> 3, c = within & 7;                                  \
            const __half* sc = tile ? vb_ : kb_;                                    \
            cp16(ds + tile * AT_OP + row * AT_ROWB + c * 16,                        \
                 sc + (size_t)row * DDIM + c * 8);                                  \
        }                                                                           \
    }

    KV_LOAD(0, 0); CP_COMMIT();
    if (nt > 1) { KV_LOAD(1, 1); } CP_COMMIT();

    const int koffV = (lane & 7) + (((lane >> 3) & 1) << 3);
    const int doffV = (lane >> 4) << 3;

    for (int t = 0; t < nt; t++) {
        CP_WAIT(1);
        __syncthreads();                     // single barrier per tile
        if (t + 2 < nt) { KV_LOAD(t + 2, (t + 2) % AT_NST); }
        CP_COMMIT();
        const uint32_t kb = s0 + (t % AT_NST) * AT_STG;

        // ---- S = Q K^T (exp2-domain scores) -------------------------------
        float S[8][4];
#pragma unroll
        for (int nj = 0; nj < 8; nj++)
#pragma unroll
            for (int c = 0; c < 4; c++) S[nj][c] = 0.f;

#pragma unroll
        for (int ks = 0; ks < 4; ks++) {
#pragma unroll
            for (int nj2 = 0; nj2 < 4; nj2++) {
                const uint32_t ad = kb + (uint32_t)(nj2 * 16 + l15) * AT_ROWB
                                    + (uint32_t)(ks * 16 + lh * 8) * 2;
                uint32_t k0, k1, k2, k3;
                LDSM_X4(k0, k1, k2, k3, ad);
                uint32_t b0[2] = {k0, k2}, b1[2] = {k1, k3};
                mma16816(S[2 * nj2], qf[ks], b0);
                mma16816(S[2 * nj2 + 1], qf[ks], b1);
            }
        }

        // ---- online softmax (base-2) --------------------------------------
        const bool masked = (t == nt - 1) || (t == nt - 2 && warp < 4);
        {
            const int row0 = qb + warp * 16 + crow;
            const int row1 = row0 + 8;
            if (masked) {
                const int colb = t * 64 + ccol;
#pragma unroll
                for (int nj = 0; nj < 8; nj++) {
                    const int c0 = colb + nj * 8;
                    if (c0 > row0)     S[nj][0] = -1e30f;
                    if (c0 + 1 > row0) S[nj][1] = -1e30f;
                    if (c0 > row1)     S[nj][2] = -1e30f;
                    if (c0 + 1 > row1) S[nj][3] = -1e30f;
                }
            }
            float mx0 = -1e30f, mx1 = -1e30f;
#pragma unroll
            for (int nj = 0; nj < 8; nj++) {
                mx0 = fmaxf(mx0, fmaxf(S[nj][0], S[nj][1]));
                mx1 = fmaxf(mx1, fmaxf(S[nj][2], S[nj][3]));
            }
            mx0 = fmaxf(mx0, __shfl_xor_sync(0xffffffff, mx0, 1));
            mx0 = fmaxf(mx0, __shfl_xor_sync(0xffffffff, mx0, 2));
            mx1 = fmaxf(mx1, __shfl_xor_sync(0xffffffff, mx1, 1));
            mx1 = fmaxf(mx1, __shfl_xor_sync(0xffffffff, mx1, 2));
            const float mn0 = fmaxf(m[0], mx0);
            const float mn1 = fmaxf(m[1], mx1);
            const float a0 = ex2f(m[0] - mn0);
            const float a1 = ex2f(m[1] - mn1);
            m[0] = mn0; m[1] = mn1;
#pragma unroll
            for (int nj = 0; nj < 8; nj++) {
                S[nj][0] = ex2f(S[nj][0] - mn0);
                S[nj][1] = ex2f(S[nj][1] - mn0);
                S[nj][2] = ex2f(S[nj][2] - mn1);
                S[nj][3] = ex2f(S[nj][3] - mn1);
            }
#pragma unroll
            for (int nj = 0; nj < 8; nj++) {
                O[nj][0] *= a0; O[nj][1] *= a0;
                O[nj][2] *= a1; O[nj][3] *= a1;
            }
            O1[0] *= a0; O1[1] *= a0; O1[2] *= a1; O1[3] *= a1;
        }

        // ---- O += P V, l += P·1 (ones-column MMA) -------------------------
        const uint32_t vb = kb + AT_OP;
#pragma unroll
        for (int ks = 0; ks < 4; ks++) {
            uint32_t pf[4];
            {
                const float* sA = S[2 * ks];
                const float* sB = S[2 * ks + 1];
                pf[0] = pack_h(sA[0], sA[1]);
                pf[1] = pack_h(sA[2], sA[3]);
                pf[2] = pack_h(sB[0], sB[1]);
                pf[3] = pack_h(sB[2], sB[3]);
            }
#pragma unroll
            for (int nj2 = 0; nj2 < 4; nj2++) {
                const uint32_t ad = vb + (uint32_t)(ks * 16 + koffV) * AT_ROWB
                                    + (uint32_t)(nj2 * 16 + doffV) * 2;
                uint32_t v0, v1, v2, v3;
                LDSM_X4_T(v0, v1, v2, v3, ad);
                uint32_t vp0[2] = {v0, v1}, vp1[2] = {v2, v3};
                mma16816(O[2 * nj2], pf, vp0);
                mma16816(O[2 * nj2 + 1], pf, vp1);
            }
            mma16816(O1, pf, bones);           // row-sum accumulator
        }
    }

    // ---- epilogue: normalize by l (= O1), store single fp16 ----------------
    {
        const float inv0 = 1.f / O1[0];
        const float inv1 = 1.f / O1[2];
        const int row0 = qb + warp * 16 + crow;
        const size_t a0 = (rb + row0) * DDIM + h * 64;
        const size_t a1 = a0 + 8 * DDIM;
#pragma unroll
        for (int nj = 0; nj < 8; nj++) {
            const int col = nj * 8 + ccol;
            *(uint32_t*)(g_att + a0 + col) = pack_h(O[nj][0] * inv0, O[nj][1] * inv0);
            *(uint32_t*)(g_att + a1 + col) = pack_h(O[nj][2] * inv1, O[nj][3] * inv1);
        }
    }
#undef KV_LOAD
}

// ---------------------------------------------------------------------------
// Inputs (metadata order): x, Wk, Wq, Wv, Wo. Output fp32 [8,1024,1024].
// ---------------------------------------------------------------------------
extern "C" void kernel_launch(void* const* d_in, const int* in_sizes, int n_in,
                              void* d_out, int out_size)
{
    const float* x  = (const float*)d_in[0];
    const float* Wk = (const float*)d_in[1];
    const float* Wq = (const float*)d_in[2];
    const float* Wv = (const float*)d_in[3];
    const float* Wo = (const float*)d_in[4];
    float* out = (float*)d_out;

    static int configured = 0;
    if (!configured) {
        cudaFuncSetAttribute(qkv_tc_kernel, cudaFuncAttributeMaxDynamicSharedMemorySize, SMEM_DYN);
        cudaFuncSetAttribute(out_tc_kernel, cudaFuncAttributeMaxDynamicSharedMemorySize, SMEM_DYN);
        cudaFuncSetAttribute(attn_tc_kernel, cudaFuncAttributeMaxDynamicSharedMemorySize, AT_SMEM);
        configured = 1;
    }

    cvt_kernel<<<8192 + 4096, 256>>>((const float4*)x, (const float4*)Wk,
                                     (const float4*)Wq, (const float4*)Wv,
                                     (const float4*)Wo);

    qkv_tc_kernel<<<dim3(8, 64, 3), 512, SMEM_DYN>>>();

    attn_tc_kernel<<<dim3(8, 128), 256, AT_SMEM>>>();

    out_tc_kernel<<<dim3(8, 64), 256, SMEM_DYN>>>(out);
}

// round 14
// speedup vs baseline: 1.0259x; 1.0259x over previous
#include <cuda_runtime.h>
#include <cuda_fp16.h>
#include <math_constants.h>
#include <cstdint>

#define TDIM   1024
#define DDIM   1024
#define NBATCH 8
#define NHEADS 16
#define MROWS  (NBATCH * TDIM)   // 8192

// Q pre-scale: 1/sqrt(64) * log2(e)  (exp2-domain softmax)
#define QSCALE 0.18033688011112042f

// ---------------- scratch (__device__ globals) ------------------------------
__device__ __align__(256) __half g_x [MROWS * DDIM];
__device__ __align__(256) __half g_q [MROWS * DDIM];
__device__ __align__(256) __half g_k [MROWS * DDIM];
__device__ __align__(256) __half g_v [MROWS * DDIM];
__device__ __align__(256) __half g_att[MROWS * DDIM];
__device__ __align__(256) __half g_wq[DDIM * DDIM];
__device__ __align__(256) __half g_wk[DDIM * DDIM];
__device__ __align__(256) __half g_wv[DDIM * DDIM];
__device__ __align__(256) __half g_wo[DDIM * DDIM];

// ---------------- PTX helpers ----------------------------------------------
__device__ __forceinline__ uint32_t smem_u32(const void* p) {
    uint32_t a;
    asm("{ .reg .u64 t; cvta.to.shared.u64 t, %1; cvt.u32.u64 %0, t; }" : "=r"(a) : "l"(p));
    return a;
}
__device__ __forceinline__ void cp16(uint32_t dst, const void* src) {
    asm volatile("cp.async.cg.shared.global [%0], [%1], 16;" :: "r"(dst), "l"(src));
}
#define CP_COMMIT()  asm volatile("cp.async.commit_group;" ::: "memory")
#define CP_WAIT(n)   asm volatile("cp.async.wait_group %0;" :: "n"(n) : "memory")

#define LDSM_X4(r0, r1, r2, r3, a)                                                 \
    asm volatile("ldmatrix.sync.aligned.m8n8.x4.shared.b16 {%0,%1,%2,%3}, [%4];"   \
                 : "=r"(r0), "=r"(r1), "=r"(r2), "=r"(r3) : "r"(a))
#define LDSM_X4_T(r0, r1, r2, r3, a)                                               \
    asm volatile("ldmatrix.sync.aligned.m8n8.x4.trans.shared.b16 {%0,%1,%2,%3}, [%4];" \
                 : "=r"(r0), "=r"(r1), "=r"(r2), "=r"(r3) : "r"(a))

__device__ __forceinline__ void mma16816(float* c, const uint32_t* a, const uint32_t* b)
{
    asm volatile(
        "mma.sync.aligned.m16n8k16.row.col.f32.f16.f16.f32 "
        "{%0,%1,%2,%3}, {%4,%5,%6,%7}, {%8,%9}, {%0,%1,%2,%3};"
        : "+f"(c[0]), "+f"(c[1]), "+f"(c[2]), "+f"(c[3])
        : "r"(a[0]), "r"(a[1]), "r"(a[2]), "r"(a[3]), "r"(b[0]), "r"(b[1]));
}

__device__ __forceinline__ uint32_t pack_h(float a, float b)
{
    __half2 H(__float2half_rn(a), __float2half_rn(b));
    return *(uint32_t*)&H;
}
__device__ __forceinline__ float ex2f(float x)
{
    float r;
    asm("ex2.approx.f32 %0, %1;" : "=f"(r) : "f"(x));
    return r;
}

// ---------------------------------------------------------------------------
// Shared GEMM smem layout constants
// ---------------------------------------------------------------------------
#define STRIDE 80
#define OPB    10240               // 128 rows * 80B
#define STGB   (2 * OPB)           // A(128), B(128)
#define NSTG   3
#define SMEM_DYN (NSTG * STGB)     // 61440

// out GEMM: A tile 256 rows
#define OPB_A2  20480              // 256 rows * 80B
#define STGB_O  (OPB_A2 + OPB)     // 30720
#define SMEM_O  (NSTG * STGB_O)    // 92160

// ---------------------------------------------------------------------------
// qkv GEMM (round-8 best config): 512 thr, 16 warps 4x4, warp tile 32x32.
// C = A · B^T, fp32 accum; epilogue: scale + single fp16 out.
// ---------------------------------------------------------------------------
__device__ __forceinline__ void hmma_gemm_qkv(const __half* __restrict__ A,
                                              const __half* __restrict__ B,
                                              __half* __restrict__ C1,
                                              float scale)
{
    extern __shared__ char smraw[];
    const uint32_t s0 = smem_u32(smraw);

    const int tid  = threadIdx.x;
    const int warp = tid >> 5;
    const int lane = tid & 31;
    const int m0   = blockIdx.y * 128;
    const int n0   = blockIdx.x * 128;
    const int wm   = (warp >> 2) * 32;
    const int wn   = (warp & 3) * 32;

    const char* ga = (const char*)(A + (size_t)m0 * DDIM);
    const char* gb = (const char*)(B + (size_t)n0 * DDIM);
    const int lrow = tid >> 2, lc = tid & 3;
    const size_t goff = (size_t)lrow * 2048 + lc * 16;
    const uint32_t soff = (uint32_t)lrow * STRIDE + lc * 16;

#define LOAD_STAGE_Q(kc, st)                                                   \
    {                                                                          \
        const uint32_t sb = s0 + (st) * STGB + soff;                           \
        const size_t go = goff + (kc) * 64;                                    \
        cp16(sb,       ga + go);                                               \
        cp16(sb + OPB, gb + go);                                               \
    }

    float acc[2][4][4];
#pragma unroll
    for (int i = 0; i < 2; i++)
#pragma unroll
        for (int j = 0; j < 4; j++)
#pragma unroll
            for (int r = 0; r < 4; r++) acc[i][j][r] = 0.f;

    LOAD_STAGE_Q(0, 0); CP_COMMIT();
    LOAD_STAGE_Q(1, 1); CP_COMMIT();

    const int arow_b = (lane & 15);
    const int ahalf  = (lane >> 4);

    for (int i = 0; i < 32; i++) {
        if (i < 30) { CP_WAIT(1); } else if (i == 30) { CP_WAIT(0); }
        __syncthreads();
        if (i < 30) { LOAD_STAGE_Q(i + 2, (i + 2) % NSTG); CP_COMMIT(); }

        const uint32_t base = s0 + (i % NSTG) * STGB;
#pragma unroll
        for (int g = 0; g < 2; g++) {
            const uint32_t coff = (uint32_t)(2 * g + ahalf) * 16;
            uint32_t af[2][4], bf[4][2];
#pragma unroll
            for (int mi = 0; mi < 2; mi++) {
                const uint32_t ra = (uint32_t)(wm + mi * 16 + arow_b) * STRIDE + coff;
                LDSM_X4(af[mi][0], af[mi][1], af[mi][2], af[mi][3], base + ra);
            }
#pragma unroll
            for (int jp = 0; jp < 2; jp++) {
                const uint32_t rbo = (uint32_t)(wn + jp * 16 + arow_b) * STRIDE + coff;
                uint32_t t0, t1, t2, t3;
                LDSM_X4(t0, t1, t2, t3, base + OPB + rbo);
                bf[2 * jp][0] = t0; bf[2 * jp][1] = t2;
                bf[2 * jp + 1][0] = t1; bf[2 * jp + 1][1] = t3;
            }
#pragma unroll
            for (int mi = 0; mi < 2; mi++)
#pragma unroll
                for (int nj = 0; nj < 4; nj++)
                    mma16816(acc[mi][nj], af[mi], bf[nj]);
        }
    }

    const int crow = lane >> 2;
    const int ccol = (lane & 3) * 2;
#pragma unroll
    for (int mi = 0; mi < 2; mi++)
#pragma unroll
        for (int nj = 0; nj < 4; nj++) {
            const size_t r0 = (size_t)(m0 + wm + mi * 16 + crow) * DDIM + (n0 + wn + nj * 8 + ccol);
            *(uint32_t*)(C1 + r0) = pack_h(acc[mi][nj][0] * scale, acc[mi][nj][1] * scale);
            *(uint32_t*)(C1 + r0 + 8 * DDIM) = pack_h(acc[mi][nj][2] * scale, acc[mi][nj][3] * scale);
        }
#undef LOAD_STAGE_Q
}

__global__ void __launch_bounds__(512, 1) qkv_tc_kernel()
{
    if (blockIdx.z == 0)                       // Q pre-scaled into exp2 domain
        hmma_gemm_qkv(g_x, g_wq, g_q, QSCALE);
    else if (blockIdx.z == 1)
        hmma_gemm_qkv(g_x, g_wk, g_k, 1.0f);
    else
        hmma_gemm_qkv(g_x, g_wv, g_v, 1.0f);
}

// ---------------------------------------------------------------------------
// out GEMM: CTA tile 256x128, 512 thr, 16 warps 4x4, warp tile 64x32.
// Grid 256 CTAs -> 1.73 waves (vs 3.46 at 128x128); keeps 16 warps/CTA.
// fp32 epilogue to d_out.
// ---------------------------------------------------------------------------
__global__ void __launch_bounds__(512, 1) out_tc_kernel(float* __restrict__ out)
{
    extern __shared__ char smraw[];
    const uint32_t s0 = smem_u32(smraw);

    const int tid  = threadIdx.x;
    const int warp = tid >> 5;
    const int lane = tid & 31;
    const int m0   = blockIdx.y * 256;
    const int n0   = blockIdx.x * 128;
    const int wm   = (warp >> 2) * 64;         // warp tile 64x32 in 256x128
    const int wn   = (warp & 3) * 32;

    const char* ga = (const char*)(g_att + (size_t)m0 * DDIM);
    const char* gb = (const char*)(g_wo  + (size_t)n0 * DDIM);
    const int lrow = tid >> 2, lc = tid & 3;            // 128 rows x 4 segs
    const size_t g0 = (size_t)lrow * 2048 + lc * 16;
    const size_t g1 = (size_t)(128 + lrow) * 2048 + lc * 16;
    const uint32_t sm0 = (uint32_t)lrow * STRIDE + lc * 16;
    const uint32_t sm1 = (uint32_t)(128 + lrow) * STRIDE + lc * 16;

#define LOAD_STAGE_O(kc, st)                                                   \
    {                                                                          \
        const uint32_t sb = s0 + (st) * STGB_O;                                \
        const size_t ko = (size_t)(kc) * 64;                                   \
        cp16(sb + sm0,          ga + g0 + ko);                                 \
        cp16(sb + sm1,          ga + g1 + ko);                                 \
        cp16(sb + OPB_A2 + sm0, gb + g0 + ko);                                 \
    }

    float acc[4][4][4];
#pragma unroll
    for (int i = 0; i < 4; i++)
#pragma unroll
        for (int j = 0; j < 4; j++)
#pragma unroll
            for (int r = 0; r < 4; r++) acc[i][j][r] = 0.f;

    LOAD_STAGE_O(0, 0); CP_COMMIT();
    LOAD_STAGE_O(1, 1); CP_COMMIT();

    const int arow_b = (lane & 15);
    const int ahalf  = (lane >> 4);

    for (int i = 0; i < 32; i++) {
        if (i < 30) { CP_WAIT(1); } else if (i == 30) { CP_WAIT(0); }
        __syncthreads();
        if (i < 30) { LOAD_STAGE_O(i + 2, (i + 2) % NSTG); CP_COMMIT(); }

        const uint32_t base = s0 + (i % NSTG) * STGB_O;
#pragma unroll
        for (int g = 0; g < 2; g++) {
            const uint32_t coff = (uint32_t)(2 * g + ahalf) * 16;
            uint32_t af[4][4], bf[4][2];
#pragma unroll
            for (int mi = 0; mi < 4; mi++) {
                const uint32_t ra = (uint32_t)(wm + mi * 16 + arow_b) * STRIDE + coff;
                LDSM_X4(af[mi][0], af[mi][1], af[mi][2], af[mi][3], base + ra);
            }
#pragma unroll
            for (int jp = 0; jp < 2; jp++) {
                const uint32_t rbo = (uint32_t)(wn + jp * 16 + arow_b) * STRIDE + coff;
                uint32_t t0, t1, t2, t3;
                LDSM_X4(t0, t1, t2, t3, base + OPB_A2 + rbo);
                bf[2 * jp][0] = t0; bf[2 * jp][1] = t2;
                bf[2 * jp + 1][0] = t1; bf[2 * jp + 1][1] = t3;
            }
#pragma unroll
            for (int mi = 0; mi < 4; mi++)
#pragma unroll
                for (int nj = 0; nj < 4; nj++)
                    mma16816(acc[mi][nj], af[mi], bf[nj]);
        }
    }

    const int crow = lane >> 2;
    const int ccol = (lane & 3) * 2;
#pragma unroll
    for (int mi = 0; mi < 4; mi++)
#pragma unroll
        for (int nj = 0; nj < 4; nj++) {
            float* p = out + (size_t)(m0 + wm + mi * 16 + crow) * DDIM + (n0 + wn + nj * 8 + ccol);
            *(float2*)p = make_float2(acc[mi][nj][0], acc[mi][nj][1]);
            *(float2*)(p + 8 * DDIM) = make_float2(acc[mi][nj][2], acc[mi][nj][3]);
        }
#undef LOAD_STAGE_O
}

// ---------------------------------------------------------------------------
// fused conversions (single fp16): blocks 0..8191 -> x, 8192.. -> weights
// ---------------------------------------------------------------------------
__global__ void __launch_bounds__(256) cvt_kernel(const float4* __restrict__ x,
                                                  const float4* __restrict__ wk,
                                                  const float4* __restrict__ wq,
                                                  const float4* __restrict__ wv,
                                                  const float4* __restrict__ wo)
{
    const int blk = blockIdx.x;
    const float4* src;
    __half* dst;
    int i;
    if (blk < 8192) {
        src = x; dst = g_x;
        i = blk * 256 + threadIdx.x;
    } else {
        const int wsel = (blk - 8192) >> 10;          // 1024 blocks per weight
        i = ((blk - 8192) & 1023) * 256 + threadIdx.x;
        switch (wsel) {
            case 0:  src = wq; dst = g_wq; break;
            case 1:  src = wk; dst = g_wk; break;
            case 2:  src = wv; dst = g_wv; break;
            default: src = wo; dst = g_wo; break;
        }
    }
    float4 v = src[i];
    ((uint32_t*)dst)[2 * i]     = pack_h(v.x, v.y);
    ((uint32_t*)dst)[2 * i + 1] = pack_h(v.z, v.w);
}

// ---------------------------------------------------------------------------
// Tensor-core causal flash attention: fp32 accum, fp16 Q/K/V/P, exp2-domain
// softmax, ones-column MMA row-sum, single __syncthreads per KV tile.
// Mask refinement: tile nt-1 masks all warps; tile nt-2 only warps 0-3.
// ---------------------------------------------------------------------------
#define AT_ROWB  144
#define AT_OP    9216              // 64 * 144
#define AT_STG   (2 * AT_OP)       // k, v
#define AT_NST   3
#define AT_SMEM  (AT_NST * AT_STG) // 55296 (covers Q staging 18432)

__global__ void __launch_bounds__(256, 2) attn_tc_kernel()
{
    extern __shared__ char smraw[];
    const uint32_t s0 = smem_u32(smraw);
    const int tid  = threadIdx.x;
    const int warp = tid >> 5;
    const int lane = tid & 31;
    const int y    = 7 - (int)blockIdx.x;      // heavy blocks first
    const int bh   = blockIdx.y;
    const int b    = bh >> 4, h = bh & 15;
    const int qb   = y * 128;
    const int nt   = 2 * y + 2;                // KV tiles of 64
    const size_t rb = (size_t)b * TDIM;

    // ---- stage Q 128x64 -> smem, then ldmatrix to regs ---------------------
    {
        const __half* src = g_q + (rb + qb) * DDIM + h * 64;
#pragma unroll
        for (int j = 0; j < 4; j++) {
            int id = tid + (j << 8);            // 0..1023
            int row = id >> 3, c = id & 7;
            cp16(s0 + row * AT_ROWB + c * 16, src + (size_t)row * DDIM + c * 8);
        }
        CP_COMMIT(); CP_WAIT(0);
        __syncthreads();
    }

    const int l15 = lane & 15, lh = lane >> 4;
    uint32_t qf[4][4];
#pragma unroll
    for (int ks = 0; ks < 4; ks++) {
        uint32_t ad = s0 + (uint32_t)(warp * 16 + l15) * AT_ROWB
                      + (uint32_t)(ks * 16 + lh * 8) * 2;
        LDSM_X4(qf[ks][0], qf[ks][1], qf[ks][2], qf[ks][3], ad);
    }
    __syncthreads();   // Q smem region free before KV loads reuse it

    float O[8][4], O1[4], m[2];
    m[0] = m[1] = -1e30f;
#pragma unroll
    for (int nj = 0; nj < 8; nj++)
#pragma unroll
        for (int c = 0; c < 4; c++) O[nj][c] = 0.f;
#pragma unroll
    for (int c = 0; c < 4; c++) O1[c] = 0.f;

    const int crow = lane >> 2, ccol = (lane & 3) * 2;
    const uint32_t ones2 = 0x3C003C00u;        // (1.0h, 1.0h)
    const uint32_t bones[2] = {ones2, ones2};

#define KV_LOAD(t, st)                                                              \
    {                                                                               \
        const __half* kb_ = g_k + (rb + (t) * 64) * DDIM + h * 64;                  \
        const __half* vb_ = g_v + (rb + (t) * 64) * DDIM + h * 64;                  \
        const uint32_t ds = s0 + (st) * AT_STG;                                     \
        _Pragma("unroll")                                                           \
        for (int j = 0; j < 4; j++) {                                               \
            int id = tid + (j << 8);                                                \
            int tile = id >> 9;                                                     \
            int within = id & 511;                                                  \
            int row = within >> 3, c = within & 7;                                  \
            const __half* sc = tile ? vb_ : kb_;                                    \
            cp16(ds + tile * AT_OP + row * AT_ROWB + c * 16,                        \
                 sc + (size_t)row * DDIM + c * 8);                                  \
        }                                                                           \
    }

    KV_LOAD(0, 0); CP_COMMIT();
    if (nt > 1) { KV_LOAD(1, 1); } CP_COMMIT();

    const int koffV = (lane & 7) + (((lane >> 3) & 1) << 3);
    const int doffV = (lane >> 4) << 3;

    for (int t = 0; t < nt; t++) {
        CP_WAIT(1);
        __syncthreads();                     // single barrier per tile
        if (t + 2 < nt) { KV_LOAD(t + 2, (t + 2) % AT_NST); }
        CP_COMMIT();
        const uint32_t kb = s0 + (t % AT_NST) * AT_STG;

        // ---- S = Q K^T (exp2-domain scores) -------------------------------
        float S[8][4];
#pragma unroll
        for (int nj = 0; nj < 8; nj++)
#pragma unroll
            for (int c = 0; c < 4; c++) S[nj][c] = 0.f;

#pragma unroll
        for (int ks = 0; ks < 4; ks++) {
#pragma unroll
            for (int nj2 = 0; nj2 < 4; nj2++) {
                const uint32_t ad = kb + (uint32_t)(nj2 * 16 + l15) * AT_ROWB
                                    + (uint32_t)(ks * 16 + lh * 8) * 2;
                uint32_t k0, k1, k2, k3;
                LDSM_X4(k0, k1, k2, k3, ad);
                uint32_t b0[2] = {k0, k2}, b1[2] = {k1, k3};
                mma16816(S[2 * nj2], qf[ks], b0);
                mma16816(S[2 * nj2 + 1], qf[ks], b1);
            }
        }

        // ---- online softmax (base-2) --------------------------------------
        const bool masked = (t == nt - 1) || (t == nt - 2 && warp < 4);
        {
            const int row0 = qb + warp * 16 + crow;
            const int row1 = row0 + 8;
            if (masked) {
                const int colb = t * 64 + ccol;
#pragma unroll
                for (int nj = 0; nj < 8; nj++) {
                    const int c0 = colb + nj * 8;
                    if (c0 > row0)     S[nj][0] = -1e30f;
                    if (c0 + 1 > row0) S[nj][1] = -1e30f;
                    if (c0 > row1)     S[nj][2] = -1e30f;
                    if (c0 + 1 > row1) S[nj][3] = -1e30f;
                }
            }
            float mx0 = -1e30f, mx1 = -1e30f;
#pragma unroll
            for (int nj = 0; nj < 8; nj++) {
                mx0 = fmaxf(mx0, fmaxf(S[nj][0], S[nj][1]));
                mx1 = fmaxf(mx1, fmaxf(S[nj][2], S[nj][3]));
            }
            mx0 = fmaxf(mx0, __shfl_xor_sync(0xffffffff, mx0, 1));
            mx0 = fmaxf(mx0, __shfl_xor_sync(0xffffffff, mx0, 2));
            mx1 = fmaxf(mx1, __shfl_xor_sync(0xffffffff, mx1, 1));
            mx1 = fmaxf(mx1, __shfl_xor_sync(0xffffffff, mx1, 2));
            const float mn0 = fmaxf(m[0], mx0);
            const float mn1 = fmaxf(m[1], mx1);
            const float a0 = ex2f(m[0] - mn0);
            const float a1 = ex2f(m[1] - mn1);
            m[0] = mn0; m[1] = mn1;
#pragma unroll
            for (int nj = 0; nj < 8; nj++) {
                S[nj][0] = ex2f(S[nj][0] - mn0);
                S[nj][1] = ex2f(S[nj][1] - mn0);
                S[nj][2] = ex2f(S[nj][2] - mn1);
                S[nj][3] = ex2f(S[nj][3] - mn1);
            }
#pragma unroll
            for (int nj = 0; nj < 8; nj++) {
                O[nj][0] *= a0; O[nj][1] *= a0;
                O[nj][2] *= a1; O[nj][3] *= a1;
            }
            O1[0] *= a0; O1[1] *= a0; O1[2] *= a1; O1[3] *= a1;
        }

        // ---- O += P V, l += P·1 (ones-column MMA) -------------------------
        const uint32_t vb = kb + AT_OP;
#pragma unroll
        for (int ks = 0; ks < 4; ks++) {
            uint32_t pf[4];
            {
                const float* sA = S[2 * ks];
                const float* sB = S[2 * ks + 1];
                pf[0] = pack_h(sA[0], sA[1]);
                pf[1] = pack_h(sA[2], sA[3]);
                pf[2] = pack_h(sB[0], sB[1]);
                pf[3] = pack_h(sB[2], sB[3]);
            }
#pragma unroll
            for (int nj2 = 0; nj2 < 4; nj2++) {
                const uint32_t ad = vb + (uint32_t)(ks * 16 + koffV) * AT_ROWB
                                    + (uint32_t)(nj2 * 16 + doffV) * 2;
                uint32_t v0, v1, v2, v3;
                LDSM_X4_T(v0, v1, v2, v3, ad);
                uint32_t vp0[2] = {v0, v1}, vp1[2] = {v2, v3};
                mma16816(O[2 * nj2], pf, vp0);
                mma16816(O[2 * nj2 + 1], pf, vp1);
            }
            mma16816(O1, pf, bones);           // row-sum accumulator
        }
    }

    // ---- epilogue: normalize by l (= O1), store single fp16 ----------------
    {
        const float inv0 = 1.f / O1[0];
        const float inv1 = 1.f / O1[2];
        const int row0 = qb + warp * 16 + crow;
        const size_t a0 = (rb + row0) * DDIM + h * 64;
        const size_t a1 = a0 + 8 * DDIM;
#pragma unroll
        for (int nj = 0; nj < 8; nj++) {
            const int col = nj * 8 + ccol;
            *(uint32_t*)(g_att + a0 + col) = pack_h(O[nj][0] * inv0, O[nj][1] * inv0);
            *(uint32_t*)(g_att + a1 + col) = pack_h(O[nj][2] * inv1, O[nj][3] * inv1);
        }
    }
#undef KV_LOAD
}

// ---------------------------------------------------------------------------
// Inputs (metadata order): x, Wk, Wq, Wv, Wo. Output fp32 [8,1024,1024].
// ---------------------------------------------------------------------------
extern "C" void kernel_launch(void* const* d_in, const int* in_sizes, int n_in,
                              void* d_out, int out_size)
{
    const float* x  = (const float*)d_in[0];
    const float* Wk = (const float*)d_in[1];
    const float* Wq = (const float*)d_in[2];
    const float* Wv = (const float*)d_in[3];
    const float* Wo = (const float*)d_in[4];
    float* out = (float*)d_out;

    static int configured = 0;
    if (!configured) {
        cudaFuncSetAttribute(qkv_tc_kernel, cudaFuncAttributeMaxDynamicSharedMemorySize, SMEM_DYN);
        cudaFuncSetAttribute(out_tc_kernel, cudaFuncAttributeMaxDynamicSharedMemorySize, SMEM_O);
        cudaFuncSetAttribute(attn_tc_kernel, cudaFuncAttributeMaxDynamicSharedMemorySize, AT_SMEM);
        configured = 1;
    }

    cvt_kernel<<<8192 + 4096, 256>>>((const float4*)x, (const float4*)Wk,
                                     (const float4*)Wq, (const float4*)Wv,
                                     (const float4*)Wo);

    qkv_tc_kernel<<<dim3(8, 64, 3), 512, SMEM_DYN>>>();

    attn_tc_kernel<<<dim3(8, 128), 256, AT_SMEM>>>();

    out_tc_kernel<<<dim3(8, 32), 512, SMEM_O>>>(out);
}